// round 7
// baseline (speedup 1.0000x reference)
#include <cuda_runtime.h>
#include <cstdint>

#define NH 32     // hidden
#define RK 6      // rank
#define BB 256    // batch
#define TT 2048   // time
#define DI 64     // input dim
#define DO 32     // output dim

#define RING  256
#define RINGM 255

// Pre-scaled x-projection scratch; oversized by one 8-step chunk so the
// A-warp prefetch needs no bounds check. (device global: allocation-free)
__device__ float g_xp[(size_t)BB * TT * NH + 8 * NH];

#define L2E2 2.885390081777926815f   // 2*log2(e)

// Packed fp32x2 ops (Blackwell)
__device__ __forceinline__ float2 fma2(const float2 a, const float2 b, const float2 c) {
    float2 d;
    asm("fma.rn.f32x2 %0, %1, %2, %3;"
        : "=l"(*(unsigned long long*)&d)
        : "l"(*(const unsigned long long*)&a),
          "l"(*(const unsigned long long*)&b),
          "l"(*(const unsigned long long*)&c));
    return d;
}
__device__ __forceinline__ float2 add2(const float2 a, const float2 b) {
    float2 d;
    asm("add.rn.f32x2 %0, %1, %2;"
        : "=l"(*(unsigned long long*)&d)
        : "l"(*(const unsigned long long*)&a),
          "l"(*(const unsigned long long*)&b));
    return d;
}

// ---------------------------------------------------------------------------
// Kernel 1: g_xp[b,t,n] = L2E2 * (sum_i inputs[b,t,i]*W_in[n,i] + bias[n])
// (proven 90us version, unchanged)
// ---------------------------------------------------------------------------
__global__ void __launch_bounds__(256) xproj_kernel(
    const float* __restrict__ inp, const float* __restrict__ Win,
    const float* __restrict__ bias)
{
    __shared__ float u[64 * DI];
    __shared__ float Wsm[NH][DI + 1];

    const int tid = threadIdx.x;

    for (int idx = tid; idx < NH * DI; idx += 256)
        Wsm[idx / DI][idx % DI] = Win[idx];

    const size_t base = (size_t)blockIdx.x * 64 * DI;
    const float4* gs = (const float4*)(inp + base);
    float4* sd = (float4*)u;
    #pragma unroll
    for (int k2 = 0; k2 < 4; k2++) sd[tid + 256 * k2] = gs[tid + 256 * k2];
    __syncthreads();

    const int n_ = tid & 31;
    const int rg = tid >> 5;

    float2 w2[DI / 2];
    #pragma unroll
    for (int i = 0; i < DI; i += 2)
        w2[i / 2] = make_float2(Wsm[n_][i], Wsm[n_][i + 1]);

    float2 acc[8];
    #pragma unroll
    for (int r = 0; r < 8; r++) acc[r] = make_float2(0.f, 0.f);

    #pragma unroll
    for (int i4 = 0; i4 < DI / 4; i4++) {
        const float2 wlo = w2[2 * i4 + 0];
        const float2 whi = w2[2 * i4 + 1];
        #pragma unroll
        for (int r = 0; r < 8; r++) {
            const float4 u4 = *(const float4*)&u[(rg * 8 + r) * DI + i4 * 4];
            acc[r] = fma2(wlo, make_float2(u4.x, u4.y), acc[r]);
            acc[r] = fma2(whi, make_float2(u4.z, u4.w), acc[r]);
        }
    }

    const float bn = bias[n_];
    const size_t rowbase = (size_t)blockIdx.x * 64;
    #pragma unroll
    for (int r = 0; r < 8; r++)
        g_xp[(rowbase + rg * 8 + r) * NH + n_] = L2E2 * (acc[r].x + acc[r].y + bn);
}

// ---------------------------------------------------------------------------
// Kernel 2: warp-specialized recurrence. One block (64 thr) per batch chain.
//   Warp A (wid 0): critical p-recurrence, writes r_t to a smem ring.
//   Warp B (wid 1): trails A, computes q/h/y from the ring.
// tanh = 1 - 2r, r = 1/(exp2(pre')+1), pre' in 2log2e-scaled space.
// A-chain: FADD(sp+b2) -> ex2 -> FADD -> rcp -> STS -> LDSx8 -> fma2 tail.
// pb = fma(0.9,p,wrsum) and b2 = pb + x_next run in the MUFU/LDS shadow.
// No per-step __syncwarp: STS/LDS are same-warp, convergent, in-order in LSU;
// asm memory clobber pins compiler ordering.
// ---------------------------------------------------------------------------
__global__ void __launch_bounds__(64) rnn_kernel(
    const float* __restrict__ m, const float* __restrict__ nv,
    const float* __restrict__ Mm, const float* __restrict__ Nm,
    const float* __restrict__ Wout, const float* __restrict__ bout,
    float* __restrict__ out, float* __restrict__ hfin)
{
    __shared__ __align__(16) float ring[RING][NH];   // 32 KB
    __shared__ unsigned progress;   // steps produced by A
    __shared__ unsigned bdone;      // steps consumed by B

    const int b   = blockIdx.x;
    const int wid = threadIdx.x >> 5;
    const int l   = threadIdx.x & 31;

    if (threadIdx.x == 0) { progress = 0u; bdone = 0u; }
    __syncthreads();

    if (wid == 0) {
        // ================= WARP A: critical chain =================
        float Ml[RK];
        const float ml = m[l];
        #pragma unroll
        for (int j = 0; j < RK; j++) Ml[j] = Mm[l * RK + j];

        float2 wr2[NH / 2];
        float wrsum = 0.f;
        #pragma unroll
        for (int k = 0; k < NH; k += 2) {
            float s0 = ml * nv[k], s1 = ml * nv[k + 1];
            #pragma unroll
            for (int j = 0; j < RK; j++) {
                s0 = fmaf(Ml[j], Nm[k * RK + j], s0);
                s1 = fmaf(Ml[j], Nm[(k + 1) * RK + j], s1);
            }
            wrsum += s0 + s1;
            wr2[k / 2] = make_float2(-0.2f * L2E2 * s0, -0.2f * L2E2 * s1);
        }
        wrsum *= 0.1f * L2E2;

        const float* xp = g_xp + (size_t)b * TT * NH + l;

        float xa[8], xn[8];
        #pragma unroll
        for (int i = 0; i < 8; i++) xa[i] = xp[(size_t)i * NH];

        // p_prev = 0 entering step 0:  sp = 0, b2 = 0 + x_0
        float sp = 0.f;
        float b2 = xa[0];

        for (int c = 0; c < TT / 8; c++) {
            const int t0 = c * 8;
            // prefetch next chunk (g_xp oversized: final reads land in slack)
            #pragma unroll
            for (int i = 0; i < 8; i++) xn[i] = xp[(size_t)(t0 + 8 + i) * NH];

            #pragma unroll
            for (int s = 0; s < 8; s++) {
                const int t = t0 + s;

                // ---- chain head ----
                const float pre = sp + b2;            // = p_{t-1} + x_t
                float e;
                asm("ex2.approx.f32 %0, %1;" : "=f"(e) : "f"(pre));
                float r;
                asm("rcp.approx.f32 %0, %1;" : "=f"(r) : "f"(e + 1.0f));

                // ---- shadow work: fold state + next x into b2 ----
                const float p  = sp + (b2 - ((s == 0) ? xa[0] : ((s < 8) ? xa[s] : 0.f)));
                // NOTE: recover p_{t-1} = sp + pb_{t-2}; cheaper: track pb explicitly below.

                ring[t & RINGM][l] = r;
                asm volatile("" ::: "memory");

                const float4* r4p = (const float4*)ring[t & RINGM];
                float2 a0, a1, a2, a3, a4, a5, a6, a7;
                {
                    const float4 q0 = r4p[0], q1 = r4p[1], q2 = r4p[2], q3 = r4p[3];
                    const float4 q4 = r4p[4], q5 = r4p[5], q6 = r4p[6], q7 = r4p[7];
                    const float2 z = make_float2(0.f, 0.f);
                    a0 = fma2(wr2[1],  make_float2(q0.z, q0.w), fma2(wr2[0],  make_float2(q0.x, q0.y), z));
                    a1 = fma2(wr2[3],  make_float2(q1.z, q1.w), fma2(wr2[2],  make_float2(q1.x, q1.y), z));
                    a2 = fma2(wr2[5],  make_float2(q2.z, q2.w), fma2(wr2[4],  make_float2(q2.x, q2.y), z));
                    a3 = fma2(wr2[7],  make_float2(q3.z, q3.w), fma2(wr2[6],  make_float2(q3.x, q3.y), z));
                    a4 = fma2(wr2[9],  make_float2(q4.z, q4.w), fma2(wr2[8],  make_float2(q4.x, q4.y), z));
                    a5 = fma2(wr2[11], make_float2(q5.z, q5.w), fma2(wr2[10], make_float2(q5.x, q5.y), z));
                    a6 = fma2(wr2[13], make_float2(q6.z, q6.w), fma2(wr2[12], make_float2(q6.x, q6.y), z));
                    a7 = fma2(wr2[15], make_float2(q7.z, q7.w), fma2(wr2[14], make_float2(q7.x, q7.y), z));
                }
                const float2 s2 = add2(add2(add2(a0, a1), add2(a2, a3)),
                                       add2(add2(a4, a5), add2(a6, a7)));

                // pb_t = 0.9*p_{t-1} + wrsum, with p_{t-1} = pre - x_t = sp + b2 - x_t.
                // Use pre directly: p_{t-1} = pre - x_t.
                const float pprev = pre - xa[s];
                const float pb    = fmaf(0.9f, pprev, wrsum);
                const float xnext = (s == 7) ? xn[0] : xa[s + 1];
                b2 = pb + xnext;                       // off-chain

                sp = s2.x + s2.y;                      // chain tail
            }
            #pragma unroll
            for (int i = 0; i < 8; i++) xa[i] = xn[i];

            if ((c & 3) == 3) {
                __threadfence_block();
                if (l == 0) {
                    *(volatile unsigned*)&progress = (unsigned)(t0 + 8);
                    while ((int)(t0 + 8) - (int)(*(volatile unsigned*)&bdone) > RING - 64)
                        __nanosleep(100);
                }
                __syncwarp();
            }
        }
    } else {
        // ================= WARP B: trailing q/h/y =================
        float2 wo2[NH / 2];
        float wosum = 0.f;
        #pragma unroll
        for (int k = 0; k < NH; k += 2) {
            const float o0 = Wout[l * NH + k], o1 = Wout[l * NH + k + 1];
            wosum += o0 + o1;
            wo2[k / 2] = make_float2(-0.2f * o0, -0.2f * o1);
        }
        wosum *= 0.1f;
        const float bo = bout[l];

        float* yo = out + (size_t)b * TT * DO + l;
        float q = 0.f, h = 0.f;

        for (int blk = 0; blk < TT / 32; blk++) {
            const int tend = (blk + 1) * 32;
            if (l == 0) {
                while ((int)(*(volatile unsigned*)&progress) < tend)
                    __nanosleep(150);
            }
            __syncwarp();
            __threadfence_block();   // acquire: ring writes visible

            for (int t = blk * 32; t < tend; t++) {
                const float4* r4p = (const float4*)ring[t & RINGM];
                float2 aq0 = make_float2(0.f, 0.f), aq1 = aq0, aq2 = aq0, aq3 = aq0;
                #pragma unroll
                for (int j = 0; j < NH / 4; j++) {
                    const float4 r4 = r4p[j];
                    const float2 lo = make_float2(r4.x, r4.y);
                    const float2 hi = make_float2(r4.z, r4.w);
                    float2 acc = (j & 3) == 0 ? aq0 : (j & 3) == 1 ? aq1 : (j & 3) == 2 ? aq2 : aq3;
                    acc = fma2(wo2[2 * j + 0], lo, acc);
                    acc = fma2(wo2[2 * j + 1], hi, acc);
                    if ((j & 3) == 0) aq0 = acc; else if ((j & 3) == 1) aq1 = acc;
                    else if ((j & 3) == 2) aq2 = acc; else aq3 = acc;
                }
                const float2 sq2 = add2(add2(aq0, aq1), add2(aq2, aq3));
                const float rl = ring[t & RINGM][l];

                q = fmaf(0.9f, q, wosum) + (sq2.x + sq2.y);
                h = fmaf(0.9f, h, 0.1f);
                h = fmaf(-0.2f, rl, h);

                yo[(size_t)t * DO] = q + bo;
            }

            if (l == 0) {
                __threadfence_block();
                *(volatile unsigned*)&bdone = (unsigned)tend;
            }
        }

        if (hfin) hfin[b * NH + l] = h;
    }
}

// ---------------------------------------------------------------------------
extern "C" void kernel_launch(void* const* d_in, const int* in_sizes, int n_in,
                              void* d_out, int out_size) {
    const float* inputs = (const float*)d_in[0];
    const float* W_in   = (const float*)d_in[1];
    const float* m_     = (const float*)d_in[2];
    const float* n_     = (const float*)d_in[3];
    const float* M_     = (const float*)d_in[4];
    const float* Nm_    = (const float*)d_in[5];
    const float* bias   = (const float*)d_in[6];
    const float* Wout   = (const float*)d_in[7];
    const float* bout   = (const float*)d_in[8];

    float* out = (float*)d_out;
    float* hf = nullptr;
    const long long need = (long long)BB * TT * NH + (long long)BB * NH;
    if ((long long)out_size >= need)
        hf = out + (size_t)BB * TT * NH;

    xproj_kernel<<<BB * TT / 64, 256>>>(inputs, W_in, bias);
    rnn_kernel<<<BB, 64>>>(m_, n_, M_, Nm_, Wout, bout, out, hf);
}

// round 9
// speedup vs baseline: 1.0034x; 1.0034x over previous
#include <cuda_runtime.h>
#include <cstdint>

#define NH 32     // hidden
#define RK 6      // rank
#define BB 256    // batch
#define TT 2048   // time
#define DI 64     // input dim
#define DO 32     // output dim

#define RING  256
#define RINGM 255

// 64 MB scratch for pre-scaled x-projection (device global: allocation-free)
__device__ float g_xp[(size_t)BB * TT * NH];

#define L2E2 2.885390081777926815f   // 2*log2(e)

// Packed fp32x2 ops (Blackwell)
__device__ __forceinline__ float2 fma2(const float2 a, const float2 b, const float2 c) {
    float2 d;
    asm("fma.rn.f32x2 %0, %1, %2, %3;"
        : "=l"(*(unsigned long long*)&d)
        : "l"(*(const unsigned long long*)&a),
          "l"(*(const unsigned long long*)&b),
          "l"(*(const unsigned long long*)&c));
    return d;
}
__device__ __forceinline__ float2 add2(const float2 a, const float2 b) {
    float2 d;
    asm("add.rn.f32x2 %0, %1, %2;"
        : "=l"(*(unsigned long long*)&d)
        : "l"(*(const unsigned long long*)&a),
          "l"(*(const unsigned long long*)&b));
    return d;
}

// ---------------------------------------------------------------------------
// Kernel 1: g_xp[b,t,n] = L2E2 * (sum_i inputs[b,t,i]*W_in[n,i] + bias[n])
// (proven 90us version, unchanged)
// ---------------------------------------------------------------------------
__global__ void __launch_bounds__(256) xproj_kernel(
    const float* __restrict__ inp, const float* __restrict__ Win,
    const float* __restrict__ bias)
{
    __shared__ float u[64 * DI];
    __shared__ float Wsm[NH][DI + 1];

    const int tid = threadIdx.x;

    for (int idx = tid; idx < NH * DI; idx += 256)
        Wsm[idx / DI][idx % DI] = Win[idx];

    const size_t base = (size_t)blockIdx.x * 64 * DI;
    const float4* gs = (const float4*)(inp + base);
    float4* sd = (float4*)u;
    #pragma unroll
    for (int k2 = 0; k2 < 4; k2++) sd[tid + 256 * k2] = gs[tid + 256 * k2];
    __syncthreads();

    const int n_ = tid & 31;
    const int rg = tid >> 5;

    float2 w2[DI / 2];
    #pragma unroll
    for (int i = 0; i < DI; i += 2)
        w2[i / 2] = make_float2(Wsm[n_][i], Wsm[n_][i + 1]);

    float2 acc[8];
    #pragma unroll
    for (int r = 0; r < 8; r++) acc[r] = make_float2(0.f, 0.f);

    #pragma unroll
    for (int i4 = 0; i4 < DI / 4; i4++) {
        const float2 wlo = w2[2 * i4 + 0];
        const float2 whi = w2[2 * i4 + 1];
        #pragma unroll
        for (int r = 0; r < 8; r++) {
            const float4 u4 = *(const float4*)&u[(rg * 8 + r) * DI + i4 * 4];
            acc[r] = fma2(wlo, make_float2(u4.x, u4.y), acc[r]);
            acc[r] = fma2(whi, make_float2(u4.z, u4.w), acc[r]);
        }
    }

    const float bn = bias[n_];
    const size_t rowbase = (size_t)blockIdx.x * 64;
    #pragma unroll
    for (int r = 0; r < 8; r++)
        g_xp[(rowbase + rg * 8 + r) * NH + n_] = L2E2 * (acc[r].x + acc[r].y + bn);
}

// ---------------------------------------------------------------------------
// Kernel 2: warp-specialized recurrence. One block (64 thr) per batch chain.
//   Warp A (wid 0): critical p-recurrence, writes r_t to a smem ring.
//   Warp B (wid 1): trails A, computes q/h/y from the ring.
// tanh = 1 - 2r, r = 1/(exp2(pre')+1), pre' in 2log2e-scaled space.
// ONE change vs the 316us kernel: no per-step __syncwarp between the ring
// STS and the broadcast LDS. Same-warp, convergent STS->LDS is processed
// in order by the LSU; asm memory clobber pins compiler ordering. Warp B's
// cross-warp handoff keeps its full fence+flag protocol.
// ---------------------------------------------------------------------------
__global__ void __launch_bounds__(64) rnn_kernel(
    const float* __restrict__ m, const float* __restrict__ nv,
    const float* __restrict__ Mm, const float* __restrict__ Nm,
    const float* __restrict__ Wout, const float* __restrict__ bout,
    float* __restrict__ out, float* __restrict__ hfin)
{
    __shared__ __align__(16) float ring[RING][NH];   // 32 KB
    __shared__ unsigned progress;   // steps produced by A
    __shared__ unsigned bdone;      // steps consumed by B

    const int b   = blockIdx.x;
    const int wid = threadIdx.x >> 5;
    const int l   = threadIdx.x & 31;

    if (threadIdx.x == 0) { progress = 0u; bdone = 0u; }
    __syncthreads();

    if (wid == 0) {
        // ================= WARP A: critical chain =================
        // wr2[k] = -0.2*L2E2*W_rec[l,k], wrsum = 0.1*L2E2*sum_k W_rec[l,k]
        float Ml[RK];
        const float ml = m[l];
        #pragma unroll
        for (int j = 0; j < RK; j++) Ml[j] = Mm[l * RK + j];

        float2 wr2[NH / 2];
        float wrsum = 0.f;
        #pragma unroll
        for (int k = 0; k < NH; k += 2) {
            float s0 = ml * nv[k], s1 = ml * nv[k + 1];
            #pragma unroll
            for (int j = 0; j < RK; j++) {
                s0 = fmaf(Ml[j], Nm[k * RK + j], s0);
                s1 = fmaf(Ml[j], Nm[(k + 1) * RK + j], s1);
            }
            wrsum += s0 + s1;
            wr2[k / 2] = make_float2(-0.2f * L2E2 * s0, -0.2f * L2E2 * s1);
        }
        wrsum *= 0.1f * L2E2;

        const float* xp = g_xp + (size_t)b * TT * NH + l;
        float p = 0.f;

        float xa[8], xn[8];
        #pragma unroll
        for (int i = 0; i < 8; i++) xa[i] = xp[(size_t)i * NH];

        for (int c = 0; c < TT / 8; c++) {
            const int t0 = c * 8;
            if (c + 1 < TT / 8) {
                #pragma unroll
                for (int i = 0; i < 8; i++) xn[i] = xp[(size_t)(t0 + 8 + i) * NH];
            }
            #pragma unroll
            for (int s = 0; s < 8; s++) {
                const int t = t0 + s;
                const float pre = p + xa[s];
                float e;
                asm("ex2.approx.f32 %0, %1;" : "=f"(e) : "f"(pre));
                float r;
                asm("rcp.approx.f32 %0, %1;" : "=f"(r) : "f"(e + 1.0f));

                const float pbase = fmaf(0.9f, p, wrsum);   // in MUFU shadow

                ring[t & RINGM][l] = r;
                asm volatile("" ::: "memory");   // compiler ordering only (no WARPSYNC)

                const float4* r4p = (const float4*)ring[t & RINGM];
                float2 ap0 = make_float2(0.f, 0.f), ap1 = ap0, ap2 = ap0, ap3 = ap0;
                #pragma unroll
                for (int j = 0; j < NH / 4; j++) {
                    const float4 r4 = r4p[j];
                    const float2 lo = make_float2(r4.x, r4.y);
                    const float2 hi = make_float2(r4.z, r4.w);
                    float2 acc = (j & 3) == 0 ? ap0 : (j & 3) == 1 ? ap1 : (j & 3) == 2 ? ap2 : ap3;
                    acc = fma2(wr2[2 * j + 0], lo, acc);
                    acc = fma2(wr2[2 * j + 1], hi, acc);
                    if ((j & 3) == 0) ap0 = acc; else if ((j & 3) == 1) ap1 = acc;
                    else if ((j & 3) == 2) ap2 = acc; else ap3 = acc;
                }
                const float2 sp2 = add2(add2(ap0, ap1), add2(ap2, ap3));
                p = pbase + (sp2.x + sp2.y);
            }
            #pragma unroll
            for (int i = 0; i < 8; i++) xa[i] = xn[i];

            if ((c & 3) == 3) {
                // publish: all A lanes fence (ring stores -> CTA scope), then flag
                __threadfence_block();
                __syncwarp();
                if (l == 0)
                    *(volatile unsigned*)&progress = (unsigned)(t0 + 8);
                // ring-overrun guard (B is faster; this never fires in practice)
                if (l == 0) {
                    while ((int)(t0 + 8) - (int)(*(volatile unsigned*)&bdone) > RING - 64)
                        __nanosleep(100);
                }
                __syncwarp();
            }
        }
    } else {
        // ================= WARP B: trailing q/h/y =================
        // wo2[k] = -0.2*W_out[l,k], wosum = 0.1*sum_k W_out[l,k]
        float2 wo2[NH / 2];
        float wosum = 0.f;
        #pragma unroll
        for (int k = 0; k < NH; k += 2) {
            const float o0 = Wout[l * NH + k], o1 = Wout[l * NH + k + 1];
            wosum += o0 + o1;
            wo2[k / 2] = make_float2(-0.2f * o0, -0.2f * o1);
        }
        wosum *= 0.1f;
        const float bo = bout[l];

        float* yo = out + (size_t)b * TT * DO + l;
        float q = 0.f, h = 0.f;

        for (int blk = 0; blk < TT / 32; blk++) {
            const int tend = (blk + 1) * 32;
            if (l == 0) {
                while ((int)(*(volatile unsigned*)&progress) < tend)
                    __nanosleep(150);
            }
            __syncwarp();
            __threadfence_block();   // acquire: ring writes visible

            for (int t = blk * 32; t < tend; t++) {
                const float4* r4p = (const float4*)ring[t & RINGM];
                float2 aq0 = make_float2(0.f, 0.f), aq1 = aq0, aq2 = aq0, aq3 = aq0;
                #pragma unroll
                for (int j = 0; j < NH / 4; j++) {
                    const float4 r4 = r4p[j];
                    const float2 lo = make_float2(r4.x, r4.y);
                    const float2 hi = make_float2(r4.z, r4.w);
                    float2 acc = (j & 3) == 0 ? aq0 : (j & 3) == 1 ? aq1 : (j & 3) == 2 ? aq2 : aq3;
                    acc = fma2(wo2[2 * j + 0], lo, acc);
                    acc = fma2(wo2[2 * j + 1], hi, acc);
                    if ((j & 3) == 0) aq0 = acc; else if ((j & 3) == 1) aq1 = acc;
                    else if ((j & 3) == 2) aq2 = acc; else aq3 = acc;
                }
                const float2 sq2 = add2(add2(aq0, aq1), add2(aq2, aq3));
                const float rl = ring[t & RINGM][l];

                q = fmaf(0.9f, q, wosum) + (sq2.x + sq2.y);
                h = fmaf(0.9f, h, 0.1f);
                h = fmaf(-0.2f, rl, h);

                yo[(size_t)t * DO] = q + bo;
            }

            if (l == 0) {
                __threadfence_block();
                *(volatile unsigned*)&bdone = (unsigned)tend;
            }
        }

        if (hfin) hfin[b * NH + l] = h;
    }
}

// ---------------------------------------------------------------------------
extern "C" void kernel_launch(void* const* d_in, const int* in_sizes, int n_in,
                              void* d_out, int out_size) {
    const float* inputs = (const float*)d_in[0];
    const float* W_in   = (const float*)d_in[1];
    const float* m_     = (const float*)d_in[2];
    const float* n_     = (const float*)d_in[3];
    const float* M_     = (const float*)d_in[4];
    const float* Nm_    = (const float*)d_in[5];
    const float* bias   = (const float*)d_in[6];
    const float* Wout   = (const float*)d_in[7];
    const float* bout   = (const float*)d_in[8];

    float* out = (float*)d_out;
    float* hf = nullptr;
    const long long need = (long long)BB * TT * NH + (long long)BB * NH;
    if ((long long)out_size >= need)
        hf = out + (size_t)BB * TT * NH;

    xproj_kernel<<<BB * TT / 64, 256>>>(inputs, W_in, bias);
    rnn_kernel<<<BB, 64>>>(m_, n_, M_, Nm_, Wout, bout, out, hf);
}